// round 14
// baseline (speedup 1.0000x reference)
#include <cuda_runtime.h>
#include <cuda_bf16.h>
#include <math.h>
#include <stdint.h>

// ---------------- problem constants ----------------
#define BB   1024
#define TT   128
#define CC   1024
#define HH   64
#define N3   192
#define KCH  32
#define NCHUNKS (CC/KCH)    // 32
#define NK16 (CC/16)        // 64
#define NTILES (N3/8)       // 24

// ---------------- smem layout (byte offsets) ----------------
// phase 1: x staging 2x(hi[128][20]u32|lo[128][20]u32) @0 (40960 B)
//          B staging 3 x 24576 B @40960 (ends 114688)
// post-projection (all dead during phase 1):
//   q_hi/q_lo/k_hi/k_lo [128][72]bf16 (pitch 144B), vt_hi/lo [64][136]bf16,
//   stats 2KB, obuf [8][16][66]f32 (overlays dead Q region in phase 4)
#define XS_PITCH   20
#define XS_BUF_U32 (2*TT*XS_PITCH)
#define STAGE_B    20480
#define BST_B      40960
#define BCHUNK_B   24576
#define Q_HI_B   0
#define Q_LO_B   18432
#define K_HI_B   36864
#define K_LO_B   55296
#define VT_HI_B  73728
#define VT_LO_B  91136
#define STATS_B  108544            // max[128][2] @ +0, sum[128][2] @ +1024
#define OBUF_B   0                 // overlays Q (dead after phase 2)
#define OB_PITCH 66
#define SMEM_BYTES 174080
#define QK_PITCH_B 144
#define VT_PITCH_B 272

// B pre-packed in m16n8k16 bf16 fragment order, hi+lo fused
__device__ __align__(16) uint4 Bfrag_g[NK16 * NTILES * 32];

// ---------------- helpers ----------------
__device__ __forceinline__ uint32_t smem_u32(const void* p) {
    uint32_t a;
    asm("{ .reg .u64 t; cvta.to.shared.u64 t, %1; cvt.u32.u64 %0, t; }" : "=r"(a) : "l"(p));
    return a;
}
__device__ __forceinline__ void split2(float a, float b, unsigned& hi, unsigned& lo) {
    __nv_bfloat16 ha = __float2bfloat16_rn(a);
    __nv_bfloat16 hb = __float2bfloat16_rn(b);
    float ra = a - __bfloat162float(ha);
    float rb = b - __bfloat162float(hb);
    __nv_bfloat16 la = __float2bfloat16_rn(ra);
    __nv_bfloat16 lb = __float2bfloat16_rn(rb);
    hi = ((unsigned)__bfloat16_as_ushort(hb) << 16) | __bfloat16_as_ushort(ha);
    lo = ((unsigned)__bfloat16_as_ushort(lb) << 16) | __bfloat16_as_ushort(la);
}
__device__ __forceinline__ void mma_bf16(float* d, const unsigned* a,
                                         unsigned b0, unsigned b1) {
    asm volatile(
        "mma.sync.aligned.m16n8k16.row.col.f32.bf16.bf16.f32 "
        "{%0,%1,%2,%3}, {%4,%5,%6,%7}, {%8,%9}, {%0,%1,%2,%3};"
        : "+f"(d[0]), "+f"(d[1]), "+f"(d[2]), "+f"(d[3])
        : "r"(a[0]), "r"(a[1]), "r"(a[2]), "r"(a[3]), "r"(b0), "r"(b1));
}
__device__ __forceinline__ void mma_bf16_k8(float* d, unsigned a0, unsigned a1,
                                            unsigned b0) {
    asm volatile(
        "mma.sync.aligned.m16n8k8.row.col.f32.bf16.bf16.f32 "
        "{%0,%1,%2,%3}, {%4,%5}, {%6}, {%0,%1,%2,%3};"
        : "+f"(d[0]), "+f"(d[1]), "+f"(d[2]), "+f"(d[3])
        : "r"(a0), "r"(a1), "r"(b0));
}
#define LDMX4(r, addr) asm volatile( \
    "ldmatrix.sync.aligned.m8n8.x4.shared.b16 {%0,%1,%2,%3}, [%4];" \
    : "=r"((r)[0]), "=r"((r)[1]), "=r"((r)[2]), "=r"((r)[3]) : "r"(addr))
#define LDMX2(r, addr) asm volatile( \
    "ldmatrix.sync.aligned.m8n8.x2.shared.b16 {%0,%1}, [%2];" \
    : "=r"((r)[0]), "=r"((r)[1]) : "r"(addr))
#define CP_ASYNC16(smem_addr, gptr) asm volatile( \
    "cp.async.cg.shared.global [%0], [%1], 16;" :: "r"(smem_addr), "l"(gptr))
#define CP_COMMIT() asm volatile("cp.async.commit_group;" ::: "memory")
#define CP_WAIT1()  asm volatile("cp.async.wait_group 1;" ::: "memory")

// ---------------- prep kernel ----------------
__global__ void prep_w(const float* __restrict__ Wk,
                       const float* __restrict__ Wq,
                       const float* __restrict__ Wv)
{
    int i = blockIdx.x * blockDim.x + threadIdx.x;
    if (i >= NK16 * NTILES * 32) return;
    int lane = i & 31;
    int rest = i >> 5;
    int nt   = rest % NTILES;
    int k16  = rest / NTILES;
    int n    = nt * 8 + (lane >> 2);
    int mat  = n >> 6;
    int h    = n & 63;
    const float* W = (mat == 0) ? Wq : (mat == 1) ? Wk : Wv;
    int kb = k16 * 16 + 2 * (lane & 3);
    float w00 = W[kb * HH + h];
    float w01 = W[(kb + 1) * HH + h];
    float w10 = W[(kb + 8) * HH + h];
    float w11 = W[(kb + 9) * HH + h];
    uint4 v;
    split2(w00, w01, v.x, v.z);
    split2(w10, w11, v.y, v.w);
    Bfrag_g[i] = v;
}

// ---------------- main fused kernel ----------------
__global__ __launch_bounds__(512, 1)
void head_attn_mma(const float* __restrict__ x, float* __restrict__ out)
{
    extern __shared__ float data[];
    const uint32_t smb = smem_u32(data);
    unsigned* xsb = (unsigned*)data;

    const int b     = blockIdx.x;
    const int tid   = threadIdx.x;
    const int warp  = tid >> 5;
    const int lane  = tid & 31;
    const int warpM = warp >> 2;
    const int warpN = warp & 3;
    const float* xb = x + (size_t)b * TT * CC;

    // ---- Phase 1: QKV projection (bf16 m16n8k16, 3-term split) ----
    float acc[2][6][4];
#pragma unroll
    for (int bk = 0; bk < 2; ++bk)
#pragma unroll
        for (int nt = 0; nt < 6; ++nt)
#pragma unroll
            for (int j = 0; j < 4; ++j) acc[bk][nt][j] = 0.f;

    const int prow0 = tid >> 3,          pj40 = tid & 7;
    const int prow1 = (tid + 512) >> 3,  pj41 = (tid + 512) & 7;
    float4 pf0 = ((const float4*)(xb + (size_t)prow0 * CC))[pj40];
    float4 pf1 = ((const float4*)(xb + (size_t)prow1 * CC))[pj41];

    {
        const uint4* g0 = Bfrag_g;
        const uint4* g1 = Bfrag_g + 2 * NTILES * 32;
        unsigned s0 = smb + BST_B;
        unsigned s1 = smb + BST_B + BCHUNK_B;
#pragma unroll
        for (int t = 0; t < 3; ++t) {
            int i = tid + t * 512;
            CP_ASYNC16(s0 + i * 16, g0 + i);
        }
        CP_COMMIT();
#pragma unroll
        for (int t = 0; t < 3; ++t) {
            int i = tid + t * 512;
            CP_ASYNC16(s1 + i * 16, g1 + i);
        }
        CP_COMMIT();
    }
    {
        unsigned* hi0 = xsb;
        unsigned* lo0 = xsb + TT * XS_PITCH;
        unsigned h, l;
        split2(pf0.x, pf0.y, h, l);
        hi0[prow0 * XS_PITCH + pj40 * 2]     = h; lo0[prow0 * XS_PITCH + pj40 * 2]     = l;
        split2(pf0.z, pf0.w, h, l);
        hi0[prow0 * XS_PITCH + pj40 * 2 + 1] = h; lo0[prow0 * XS_PITCH + pj40 * 2 + 1] = l;
        split2(pf1.x, pf1.y, h, l);
        hi0[prow1 * XS_PITCH + pj41 * 2]     = h; lo0[prow1 * XS_PITCH + pj41 * 2]     = l;
        split2(pf1.z, pf1.w, h, l);
        hi0[prow1 * XS_PITCH + pj41 * 2 + 1] = h; lo0[prow1 * XS_PITCH + pj41 * 2 + 1] = l;
    }
    pf0 = ((const float4*)(xb + (size_t)prow0 * CC + KCH))[pj40];
    pf1 = ((const float4*)(xb + (size_t)prow1 * CC + KCH))[pj41];
    CP_WAIT1();
    __syncthreads();

    const unsigned a_off = (unsigned)((warpM * 32 + (lane & 15)) * 80 + (lane >> 4) * 16);

    int bbuf = 0;
    for (int ch = 0; ch < NCHUNKS; ++ch) {
        if (ch + 2 < NCHUNKS) {
            int nb = bbuf + 2; if (nb >= 3) nb -= 3;
            const uint4* gsrc = Bfrag_g + (size_t)(ch + 2) * 2 * NTILES * 32;
            unsigned sdst = smb + BST_B + (unsigned)(nb * BCHUNK_B);
#pragma unroll
            for (int t = 0; t < 3; ++t) {
                int i = tid + t * 512;
                CP_ASYNC16(sdst + i * 16, gsrc + i);
            }
        }
        CP_COMMIT();

        if (ch + 1 < NCHUNKS) {
            unsigned* hin = xsb + ((ch + 1) & 1) * XS_BUF_U32;
            unsigned* lon = hin + TT * XS_PITCH;
            unsigned h, l;
            split2(pf0.x, pf0.y, h, l);
            hin[prow0 * XS_PITCH + pj40 * 2]     = h; lon[prow0 * XS_PITCH + pj40 * 2]     = l;
            split2(pf0.z, pf0.w, h, l);
            hin[prow0 * XS_PITCH + pj40 * 2 + 1] = h; lon[prow0 * XS_PITCH + pj40 * 2 + 1] = l;
            split2(pf1.x, pf1.y, h, l);
            hin[prow1 * XS_PITCH + pj41 * 2]     = h; lon[prow1 * XS_PITCH + pj41 * 2]     = l;
            split2(pf1.z, pf1.w, h, l);
            hin[prow1 * XS_PITCH + pj41 * 2 + 1] = h; lon[prow1 * XS_PITCH + pj41 * 2 + 1] = l;
        }
        if (ch + 2 < NCHUNKS) {
            int c0n = (ch + 2) * KCH;
            pf0 = ((const float4*)(xb + (size_t)prow0 * CC + c0n))[pj40];
            pf1 = ((const float4*)(xb + (size_t)prow1 * CC + c0n))[pj41];
        }

        const unsigned hib = smb + (unsigned)((ch & 1) * STAGE_B);
        const unsigned lob = hib + TT * XS_PITCH * 4;
        const uint4* bbase = (const uint4*)((char*)data + BST_B + bbuf * BCHUNK_B);
#pragma unroll
        for (int g = 0; g < 2; ++g) {
            unsigned ah0[4], al0[4], ah1[4], al1[4];
            unsigned ad  = hib + a_off + g * 32;
            unsigned al_ = lob + a_off + g * 32;
            LDMX4(ah0, ad);
            LDMX4(al0, al_);
            LDMX4(ah1, ad + 16 * 80);
            LDMX4(al1, al_ + 16 * 80);

            const uint4* bp = bbase + (g * NTILES + warpN * 6) * 32 + lane;
#pragma unroll
            for (int nt = 0; nt < 6; ++nt) {
                uint4 b4 = bp[nt * 32];
                mma_bf16(acc[0][nt], ah0, b4.x, b4.y);
                mma_bf16(acc[0][nt], al0, b4.x, b4.y);
                mma_bf16(acc[0][nt], ah0, b4.z, b4.w);
                mma_bf16(acc[1][nt], ah1, b4.x, b4.y);
                mma_bf16(acc[1][nt], al1, b4.x, b4.y);
                mma_bf16(acc[1][nt], ah1, b4.z, b4.w);
            }
        }

        CP_WAIT1();
        __syncthreads();
        if (++bbuf == 3) bbuf = 0;
    }

    // ---- scatter: Q/K -> bf16 hi/lo rows; V -> vt[h][s] bf16 hi/lo ----
    {
        char* base = (char*)data;
#pragma unroll
        for (int bk = 0; bk < 2; ++bk) {
#pragma unroll
            for (int nt = 0; nt < 6; ++nt) {
                int r   = warpM * 32 + bk * 16 + (lane >> 2);
                int n   = warpN * 48 + nt * 8 + (lane & 3) * 2;
                int mat = n >> 6;
                int h   = n & 63;
                unsigned hiA, loA, hiB, loB;
                split2(acc[bk][nt][0], acc[bk][nt][1], hiA, loA);
                split2(acc[bk][nt][2], acc[bk][nt][3], hiB, loB);
                if (mat == 0) {
                    *(unsigned*)(base + Q_HI_B + r * QK_PITCH_B + h * 2)       = hiA;
                    *(unsigned*)(base + Q_LO_B + r * QK_PITCH_B + h * 2)       = loA;
                    *(unsigned*)(base + Q_HI_B + (r + 8) * QK_PITCH_B + h * 2) = hiB;
                    *(unsigned*)(base + Q_LO_B + (r + 8) * QK_PITCH_B + h * 2) = loB;
                } else if (mat == 1) {
                    *(unsigned*)(base + K_HI_B + r * QK_PITCH_B + h * 2)       = hiA;
                    *(unsigned*)(base + K_LO_B + r * QK_PITCH_B + h * 2)       = loA;
                    *(unsigned*)(base + K_HI_B + (r + 8) * QK_PITCH_B + h * 2) = hiB;
                    *(unsigned*)(base + K_LO_B + (r + 8) * QK_PITCH_B + h * 2) = loB;
                } else {
                    *(unsigned short*)(base + VT_HI_B + h * VT_PITCH_B + r * 2)             = (unsigned short)(hiA & 0xFFFF);
                    *(unsigned short*)(base + VT_HI_B + (h + 1) * VT_PITCH_B + r * 2)       = (unsigned short)(hiA >> 16);
                    *(unsigned short*)(base + VT_LO_B + h * VT_PITCH_B + r * 2)             = (unsigned short)(loA & 0xFFFF);
                    *(unsigned short*)(base + VT_LO_B + (h + 1) * VT_PITCH_B + r * 2)       = (unsigned short)(loA >> 16);
                    *(unsigned short*)(base + VT_HI_B + h * VT_PITCH_B + (r + 8) * 2)       = (unsigned short)(hiB & 0xFFFF);
                    *(unsigned short*)(base + VT_HI_B + (h + 1) * VT_PITCH_B + (r + 8) * 2) = (unsigned short)(hiB >> 16);
                    *(unsigned short*)(base + VT_LO_B + h * VT_PITCH_B + (r + 8) * 2)       = (unsigned short)(loB & 0xFFFF);
                    *(unsigned short*)(base + VT_LO_B + (h + 1) * VT_PITCH_B + (r + 8) * 2) = (unsigned short)(loB >> 16);
                }
            }
        }
    }
    __syncthreads();

    // ================= FA2-style tail: S, softmax, O all register-resident =====
    const int tb = warp >> 1;           // row-block 0..7 (rows tb*16..+15)
    const int nh = warp & 1;            // n-half: nt in [nh*8, nh*8+7]
    const int nt_lo = nh * 8;
    const int nt_hi_c = 2 * tb + 1;     // causal max nt
    int na = nt_hi_c - nt_lo + 1;
    if (na < 0) na = 0; if (na > 8) na = 8;
    const int r1 = tb * 16 + (lane >> 2);
    const int r2 = r1 + 8;

    // ---- Phase 2: S = Q @ K^T into registers ----
    float sacc[8][4];
#pragma unroll
    for (int j = 0; j < 8; ++j)
#pragma unroll
        for (int q = 0; q < 4; ++q) sacc[j][q] = 0.f;
    {
        const unsigned aqb = smb + Q_HI_B + (unsigned)((tb * 16 + (lane & 15)) * QK_PITCH_B)
                           + (lane >> 4) * 16;
        const unsigned akb = smb + K_HI_B + (unsigned)(((lane & 7)) * QK_PITCH_B)
                           + ((lane >> 3) & 1) * 16;
#pragma unroll
        for (int kg = 0; kg < 4; ++kg) {
            unsigned qh[4], ql[4];
            LDMX4(qh, aqb + kg * 32);
            LDMX4(ql, aqb + kg * 32 + (Q_LO_B - Q_HI_B));
#pragma unroll
            for (int j = 0; j < 8; ++j) {
                if (j < na) {
                    int nt = nt_lo + j;
                    unsigned kh[2], kl[2];
                    unsigned ka = akb + (unsigned)(nt * 8 * QK_PITCH_B) + kg * 32;
                    LDMX2(kh, ka);
                    LDMX2(kl, ka + (K_LO_B - K_HI_B));
                    mma_bf16(sacc[j], qh, kh[0], kh[1]);
                    mma_bf16(sacc[j], ql, kh[0], kh[1]);
                    mma_bf16(sacc[j], qh, kl[0], kl[1]);
                }
            }
        }
    }

    // ---- Phase 3: causal mask + softmax (regs + 2KB stats smem) ----
    float* smax = (float*)((char*)data + STATS_B);
    float* ssum = (float*)((char*)data + STATS_B + 1024);
    float m1l = -INFINITY, m2l = -INFINITY;
#pragma unroll
    for (int j = 0; j < 8; ++j) {
        if (j < na) {
            int c = (nt_lo + j) * 8 + 2 * (lane & 3);
            if (c > r1)     sacc[j][0] = -INFINITY;
            if (c + 1 > r1) sacc[j][1] = -INFINITY;
            if (c > r2)     sacc[j][2] = -INFINITY;
            if (c + 1 > r2) sacc[j][3] = -INFINITY;
            m1l = fmaxf(m1l, fmaxf(sacc[j][0], sacc[j][1]));
            m2l = fmaxf(m2l, fmaxf(sacc[j][2], sacc[j][3]));
        }
    }
    m1l = fmaxf(m1l, __shfl_xor_sync(0xffffffffu, m1l, 1));
    m1l = fmaxf(m1l, __shfl_xor_sync(0xffffffffu, m1l, 2));
    m2l = fmaxf(m2l, __shfl_xor_sync(0xffffffffu, m2l, 1));
    m2l = fmaxf(m2l, __shfl_xor_sync(0xffffffffu, m2l, 2));
    if ((lane & 3) == 0) { smax[r1 * 2 + nh] = m1l; smax[r2 * 2 + nh] = m2l; }
    __syncthreads();
    float m1 = fmaxf(smax[r1 * 2], smax[r1 * 2 + 1]);
    float m2 = fmaxf(smax[r2 * 2], smax[r2 * 2 + 1]);
    float s1 = 0.f, s2 = 0.f;
#pragma unroll
    for (int j = 0; j < 8; ++j) {
        if (j < na) {
            sacc[j][0] = __expf(sacc[j][0] - m1);
            sacc[j][1] = __expf(sacc[j][1] - m1);
            sacc[j][2] = __expf(sacc[j][2] - m2);
            sacc[j][3] = __expf(sacc[j][3] - m2);
            s1 += sacc[j][0] + sacc[j][1];
            s2 += sacc[j][2] + sacc[j][3];
        }
    }
    s1 += __shfl_xor_sync(0xffffffffu, s1, 1);
    s1 += __shfl_xor_sync(0xffffffffu, s1, 2);
    s2 += __shfl_xor_sync(0xffffffffu, s2, 1);
    s2 += __shfl_xor_sync(0xffffffffu, s2, 2);
    if ((lane & 3) == 0) { ssum[r1 * 2 + nh] = s1; ssum[r2 * 2 + nh] = s2; }
    __syncthreads();
    float inv1 = 1.f / (ssum[r1 * 2] + ssum[r1 * 2 + 1]);
    float inv2 = 1.f / (ssum[r2 * 2] + ssum[r2 * 2 + 1]);

    // P -> bf16 hi/lo register fragments (A-operand layout for m16n8k8)
    unsigned phi[16], plo[16];
#pragma unroll
    for (int j = 0; j < 8; ++j) {
        if (j < na) {
            split2(sacc[j][0] * inv1, sacc[j][1] * inv1, phi[2 * j],     plo[2 * j]);
            split2(sacc[j][2] * inv2, sacc[j][3] * inv2, phi[2 * j + 1], plo[2 * j + 1]);
        } else {
            phi[2 * j] = 0; plo[2 * j] = 0; phi[2 * j + 1] = 0; plo[2 * j + 1] = 0;
        }
    }

    // ---- Phase 4: O = P @ V via m16n8k8, A from registers ----
    float oacc[8][4];
#pragma unroll
    for (int t = 0; t < 8; ++t)
#pragma unroll
        for (int q = 0; q < 4; ++q) oacc[t][q] = 0.f;
    {
        const unsigned avb = smb + VT_HI_B + (unsigned)((lane & 7) * VT_PITCH_B)
                           + ((lane >> 3) & 1) * 16;
#pragma unroll
        for (int j = 0; j < 8; j += 2) {
            if (j < na) {                       // na is even
                int kg = nt_lo + j;
#pragma unroll
                for (int th = 0; th < 8; ++th) {
                    unsigned vh[2], vl[2];
                    unsigned va = avb + (unsigned)(th * 8 * VT_PITCH_B) + kg * 16;
                    LDMX2(vh, va);
                    LDMX2(vl, va + (VT_LO_B - VT_HI_B));
                    mma_bf16_k8(oacc[th], phi[2 * j],     phi[2 * j + 1],     vh[0]);
                    mma_bf16_k8(oacc[th], plo[2 * j],     plo[2 * j + 1],     vh[0]);
                    mma_bf16_k8(oacc[th], phi[2 * j],     phi[2 * j + 1],     vl[0]);
                    mma_bf16_k8(oacc[th], phi[2 * j + 2], phi[2 * j + 3],     vh[1]);
                    mma_bf16_k8(oacc[th], plo[2 * j + 2], plo[2 * j + 3],     vh[1]);
                    mma_bf16_k8(oacc[th], phi[2 * j + 2], phi[2 * j + 3],     vl[1]);
                }
            }
        }
    }

    // ---- combine n-half partials via obuf, then STG ----
    {
        float* obuf = (float*)((char*)data + OBUF_B) + tb * 16 * OB_PITCH;
        int rl = lane >> 2;
        int hc = 2 * (lane & 3);
        if (nh == 0) {
#pragma unroll
            for (int th = 0; th < 8; ++th) {
                int h = th * 8 + hc;
                *(float2*)&obuf[rl * OB_PITCH + h]       = make_float2(oacc[th][0], oacc[th][1]);
                *(float2*)&obuf[(rl + 8) * OB_PITCH + h] = make_float2(oacc[th][2], oacc[th][3]);
            }
        }
        __syncthreads();
        if (nh == 1) {
            float* ob = out + (size_t)b * TT * HH;
#pragma unroll
            for (int th = 0; th < 8; ++th) {
                int h = th * 8 + hc;
                float2 p1 = *(float2*)&obuf[rl * OB_PITCH + h];
                float2 p2 = *(float2*)&obuf[(rl + 8) * OB_PITCH + h];
                *(float2*)&ob[r1 * HH + h] = make_float2(p1.x + oacc[th][0], p1.y + oacc[th][1]);
                *(float2*)&ob[r2 * HH + h] = make_float2(p2.x + oacc[th][2], p2.y + oacc[th][3]);
            }
        }
    }
}

extern "C" void kernel_launch(void* const* d_in, const int* in_sizes, int n_in,
                              void* d_out, int out_size)
{
    const float* x  = (const float*)d_in[0];
    const float* Wk = (const float*)d_in[1];
    const float* Wq = (const float*)d_in[2];
    const float* Wv = (const float*)d_in[3];
    float* out = (float*)d_out;

    static int smem_set = 0;
    if (!smem_set) {
        cudaFuncSetAttribute(head_attn_mma,
                             cudaFuncAttributeMaxDynamicSharedMemorySize,
                             SMEM_BYTES);
        smem_set = 1;
    }
    prep_w<<<(NK16 * NTILES * 32 + 255) / 256, 256>>>(Wk, Wq, Wv);
    head_attn_mma<<<BB, 512, SMEM_BYTES>>>(x, out);
}

// round 16
// speedup vs baseline: 1.0173x; 1.0173x over previous
#include <cuda_runtime.h>
#include <cuda_bf16.h>
#include <math.h>
#include <stdint.h>

// ---------------- problem constants ----------------
#define BB   1024
#define TT   128
#define CC   1024
#define HH   64
#define N3   192
#define KCH  64
#define NCHUNKS (CC/KCH)    // 16
#define NK16 (CC/16)        // 64
#define NTILES (N3/8)       // 24

// ---------------- smem layout (byte offsets) ----------------
// phase 1: x staging 2 bufs x (hi[128][36]u32 | lo[128][36]u32) @0  (73728 B)
//          B staging 2 x 49152 B @73728 (ends 172032)
// post-projection (dead during phase 1):
//   q_hi/q_lo/k_hi/k_lo [128][72]bf16 (pitch 144B), vt_hi/lo [64][136]bf16,
//   stats 2KB, obuf overlays Q
#define XS_PITCH   36
#define XS_HALF_B  18432               // 128*36*4
#define XS_BUF_B   36864               // hi+lo
#define BST_B      73728
#define BCHUNK_B   49152               // 4 k16 * 24 nt * 32 lanes * 16B
#define Q_HI_B   0
#define Q_LO_B   18432
#define K_HI_B   36864
#define K_LO_B   55296
#define VT_HI_B  73728
#define VT_LO_B  91136
#define STATS_B  108544
#define OBUF_B   0
#define OB_PITCH 66
#define SMEM_BYTES 172032
#define QK_PITCH_B 144
#define VT_PITCH_B 272

// B pre-packed in m16n8k16 bf16 fragment order, hi+lo fused
__device__ __align__(16) uint4 Bfrag_g[NK16 * NTILES * 32];

// ---------------- helpers ----------------
__device__ __forceinline__ uint32_t smem_u32(const void* p) {
    uint32_t a;
    asm("{ .reg .u64 t; cvta.to.shared.u64 t, %1; cvt.u32.u64 %0, t; }" : "=r"(a) : "l"(p));
    return a;
}
__device__ __forceinline__ void split2(float a, float b, unsigned& hi, unsigned& lo) {
    __nv_bfloat16 ha = __float2bfloat16_rn(a);
    __nv_bfloat16 hb = __float2bfloat16_rn(b);
    float ra = a - __bfloat162float(ha);
    float rb = b - __bfloat162float(hb);
    __nv_bfloat16 la = __float2bfloat16_rn(ra);
    __nv_bfloat16 lb = __float2bfloat16_rn(rb);
    hi = ((unsigned)__bfloat16_as_ushort(hb) << 16) | __bfloat16_as_ushort(ha);
    lo = ((unsigned)__bfloat16_as_ushort(lb) << 16) | __bfloat16_as_ushort(la);
}
__device__ __forceinline__ void mma_bf16(float* d, const unsigned* a,
                                         unsigned b0, unsigned b1) {
    asm volatile(
        "mma.sync.aligned.m16n8k16.row.col.f32.bf16.bf16.f32 "
        "{%0,%1,%2,%3}, {%4,%5,%6,%7}, {%8,%9}, {%0,%1,%2,%3};"
        : "+f"(d[0]), "+f"(d[1]), "+f"(d[2]), "+f"(d[3])
        : "r"(a[0]), "r"(a[1]), "r"(a[2]), "r"(a[3]), "r"(b0), "r"(b1));
}
__device__ __forceinline__ void mma_bf16_k8(float* d, unsigned a0, unsigned a1,
                                            unsigned b0) {
    asm volatile(
        "mma.sync.aligned.m16n8k8.row.col.f32.bf16.bf16.f32 "
        "{%0,%1,%2,%3}, {%4,%5}, {%6}, {%0,%1,%2,%3};"
        : "+f"(d[0]), "+f"(d[1]), "+f"(d[2]), "+f"(d[3])
        : "r"(a0), "r"(a1), "r"(b0));
}
#define LDMX4(r, addr) asm volatile( \
    "ldmatrix.sync.aligned.m8n8.x4.shared.b16 {%0,%1,%2,%3}, [%4];" \
    : "=r"((r)[0]), "=r"((r)[1]), "=r"((r)[2]), "=r"((r)[3]) : "r"(addr))
#define LDMX2(r, addr) asm volatile( \
    "ldmatrix.sync.aligned.m8n8.x2.shared.b16 {%0,%1}, [%2];" \
    : "=r"((r)[0]), "=r"((r)[1]) : "r"(addr))
#define CP_ASYNC16(smem_addr, gptr) asm volatile( \
    "cp.async.cg.shared.global [%0], [%1], 16;" :: "r"(smem_addr), "l"(gptr))
#define CP_COMMIT() asm volatile("cp.async.commit_group;" ::: "memory")
#define CP_WAIT0()  asm volatile("cp.async.wait_group 0;" ::: "memory")

// ---------------- prep kernel ----------------
__global__ void prep_w(const float* __restrict__ Wk,
                       const float* __restrict__ Wq,
                       const float* __restrict__ Wv)
{
    int i = blockIdx.x * blockDim.x + threadIdx.x;
    if (i >= NK16 * NTILES * 32) return;
    int lane = i & 31;
    int rest = i >> 5;
    int nt   = rest % NTILES;
    int k16  = rest / NTILES;
    int n    = nt * 8 + (lane >> 2);
    int mat  = n >> 6;
    int h    = n & 63;
    const float* W = (mat == 0) ? Wq : (mat == 1) ? Wk : Wv;
    int kb = k16 * 16 + 2 * (lane & 3);
    float w00 = W[kb * HH + h];
    float w01 = W[(kb + 1) * HH + h];
    float w10 = W[(kb + 8) * HH + h];
    float w11 = W[(kb + 9) * HH + h];
    uint4 v;
    split2(w00, w01, v.x, v.z);
    split2(w10, w11, v.y, v.w);
    Bfrag_g[i] = v;
}

// ---------------- main fused kernel ----------------
__global__ __launch_bounds__(512, 1)
void head_attn_mma(const float* __restrict__ x, float* __restrict__ out)
{
    extern __shared__ float data[];
    const uint32_t smb = smem_u32(data);

    const int b     = blockIdx.x;
    const int tid   = threadIdx.x;
    const int warp  = tid >> 5;
    const int lane  = tid & 31;
    const int warpM = warp >> 2;
    const int warpN = warp & 3;
    const float* xb = x + (size_t)b * TT * CC;

    // ---- Phase 1: QKV projection (bf16 m16n8k16, 3-term split) ----
    float acc[2][6][4];
#pragma unroll
    for (int bk = 0; bk < 2; ++bk)
#pragma unroll
        for (int nt = 0; nt < 6; ++nt)
#pragma unroll
            for (int j = 0; j < 4; ++j) acc[bk][nt][j] = 0.f;

    // each thread loads 4 float4 per 64-col chunk: row tid>>2, quads (tid&3)+4e
    const int prow = tid >> 2;
    const int q0   = tid & 3;
    float4 pf[4];
#pragma unroll
    for (int e = 0; e < 4; ++e)
        pf[e] = ((const float4*)(xb + (size_t)prow * CC))[q0 + 4 * e];

    // prologue: cp.async B(0); stage x(0); prefetch x(1)
    {
        const uint4* g0 = Bfrag_g;
        unsigned s0 = smb + BST_B;
#pragma unroll
        for (int t = 0; t < 6; ++t) {
            int i = tid + t * 512;
            CP_ASYNC16(s0 + i * 16, g0 + i);
        }
        CP_COMMIT();
    }
    {
        unsigned* hi0 = (unsigned*)data;
        unsigned* lo0 = (unsigned*)((char*)data + XS_HALF_B);
#pragma unroll
        for (int e = 0; e < 4; ++e) {
            int j4 = q0 + 4 * e;
            unsigned h, l;
            split2(pf[e].x, pf[e].y, h, l);
            hi0[prow * XS_PITCH + j4 * 2]     = h; lo0[prow * XS_PITCH + j4 * 2]     = l;
            split2(pf[e].z, pf[e].w, h, l);
            hi0[prow * XS_PITCH + j4 * 2 + 1] = h; lo0[prow * XS_PITCH + j4 * 2 + 1] = l;
        }
    }
#pragma unroll
    for (int e = 0; e < 4; ++e)
        pf[e] = ((const float4*)(xb + (size_t)prow * CC + KCH))[q0 + 4 * e];
    CP_WAIT0();
    __syncthreads();

    const unsigned a_off = (unsigned)((warpM * 32 + (lane & 15)) * (XS_PITCH * 4)
                                      + (lane >> 4) * 16);

    for (int ch = 0; ch < NCHUNKS; ++ch) {
        // cp.async B(ch+1) into the other buffer (read last at ch-1; barrier-safe)
        if (ch + 1 < NCHUNKS) {
            const uint4* gsrc = Bfrag_g + (size_t)(ch + 1) * 4 * NTILES * 32;
            unsigned sdst = smb + BST_B + (unsigned)(((ch + 1) & 1) * BCHUNK_B);
#pragma unroll
            for (int t = 0; t < 6; ++t) {
                int i = tid + t * 512;
                CP_ASYNC16(sdst + i * 16, gsrc + i);
            }
        }
        CP_COMMIT();

        // stage x(ch+1) from prefetch regs
        if (ch + 1 < NCHUNKS) {
            unsigned* hin = (unsigned*)((char*)data + ((ch + 1) & 1) * XS_BUF_B);
            unsigned* lon = (unsigned*)((char*)hin + XS_HALF_B);
#pragma unroll
            for (int e = 0; e < 4; ++e) {
                int j4 = q0 + 4 * e;
                unsigned h, l;
                split2(pf[e].x, pf[e].y, h, l);
                hin[prow * XS_PITCH + j4 * 2]     = h; lon[prow * XS_PITCH + j4 * 2]     = l;
                split2(pf[e].z, pf[e].w, h, l);
                hin[prow * XS_PITCH + j4 * 2 + 1] = h; lon[prow * XS_PITCH + j4 * 2 + 1] = l;
            }
        }
        if (ch + 2 < NCHUNKS) {
            int c0n = (ch + 2) * KCH;
#pragma unroll
            for (int e = 0; e < 4; ++e)
                pf[e] = ((const float4*)(xb + (size_t)prow * CC + c0n))[q0 + 4 * e];
        }

        // compute chunk ch: 4 k16-groups x 6 nt x 6 MMAs (acc0/acc1 interleaved)
        const unsigned hib = smb + (unsigned)((ch & 1) * XS_BUF_B);
        const unsigned lob = hib + XS_HALF_B;
        const uint4* bbase = (const uint4*)((char*)data + BST_B + (ch & 1) * BCHUNK_B);
#pragma unroll
        for (int g = 0; g < 4; ++g) {
            unsigned ah0[4], al0[4], ah1[4], al1[4];
            unsigned ad  = hib + a_off + g * 32;
            unsigned al_ = lob + a_off + g * 32;
            LDMX4(ah0, ad);
            LDMX4(al0, al_);
            LDMX4(ah1, ad + 16 * (XS_PITCH * 4));
            LDMX4(al1, al_ + 16 * (XS_PITCH * 4));

            const uint4* bp = bbase + (g * NTILES + warpN * 6) * 32 + lane;
#pragma unroll
            for (int nt = 0; nt < 6; ++nt) {
                uint4 b4 = bp[nt * 32];
                mma_bf16(acc[0][nt], ah0, b4.x, b4.y);
                mma_bf16(acc[1][nt], ah1, b4.x, b4.y);
                mma_bf16(acc[0][nt], al0, b4.x, b4.y);
                mma_bf16(acc[1][nt], al1, b4.x, b4.y);
                mma_bf16(acc[0][nt], ah0, b4.z, b4.w);
                mma_bf16(acc[1][nt], ah1, b4.z, b4.w);
            }
        }

        CP_WAIT0();
        __syncthreads();
    }

    // ---- scatter: Q/K -> bf16 hi/lo rows; V -> vt[h][s] bf16 hi/lo ----
    {
        char* base = (char*)data;
#pragma unroll
        for (int bk = 0; bk < 2; ++bk) {
#pragma unroll
            for (int nt = 0; nt < 6; ++nt) {
                int r   = warpM * 32 + bk * 16 + (lane >> 2);
                int n   = warpN * 48 + nt * 8 + (lane & 3) * 2;
                int mat = n >> 6;
                int h   = n & 63;
                unsigned hiA, loA, hiB, loB;
                split2(acc[bk][nt][0], acc[bk][nt][1], hiA, loA);
                split2(acc[bk][nt][2], acc[bk][nt][3], hiB, loB);
                if (mat == 0) {
                    *(unsigned*)(base + Q_HI_B + r * QK_PITCH_B + h * 2)       = hiA;
                    *(unsigned*)(base + Q_LO_B + r * QK_PITCH_B + h * 2)       = loA;
                    *(unsigned*)(base + Q_HI_B + (r + 8) * QK_PITCH_B + h * 2) = hiB;
                    *(unsigned*)(base + Q_LO_B + (r + 8) * QK_PITCH_B + h * 2) = loB;
                } else if (mat == 1) {
                    *(unsigned*)(base + K_HI_B + r * QK_PITCH_B + h * 2)       = hiA;
                    *(unsigned*)(base + K_LO_B + r * QK_PITCH_B + h * 2)       = loA;
                    *(unsigned*)(base + K_HI_B + (r + 8) * QK_PITCH_B + h * 2) = hiB;
                    *(unsigned*)(base + K_LO_B + (r + 8) * QK_PITCH_B + h * 2) = loB;
                } else {
                    *(unsigned short*)(base + VT_HI_B + h * VT_PITCH_B + r * 2)             = (unsigned short)(hiA & 0xFFFF);
                    *(unsigned short*)(base + VT_HI_B + (h + 1) * VT_PITCH_B + r * 2)       = (unsigned short)(hiA >> 16);
                    *(unsigned short*)(base + VT_LO_B + h * VT_PITCH_B + r * 2)             = (unsigned short)(loA & 0xFFFF);
                    *(unsigned short*)(base + VT_LO_B + (h + 1) * VT_PITCH_B + r * 2)       = (unsigned short)(loA >> 16);
                    *(unsigned short*)(base + VT_HI_B + h * VT_PITCH_B + (r + 8) * 2)       = (unsigned short)(hiB & 0xFFFF);
                    *(unsigned short*)(base + VT_HI_B + (h + 1) * VT_PITCH_B + (r + 8) * 2) = (unsigned short)(hiB >> 16);
                    *(unsigned short*)(base + VT_LO_B + h * VT_PITCH_B + (r + 8) * 2)       = (unsigned short)(loB & 0xFFFF);
                    *(unsigned short*)(base + VT_LO_B + (h + 1) * VT_PITCH_B + (r + 8) * 2) = (unsigned short)(loB >> 16);
                }
            }
        }
    }
    __syncthreads();

    // ================= FA2-style tail (unchanged from R13) =====================
    const int tb = warp >> 1;
    const int nh = warp & 1;
    const int nt_lo = nh * 8;
    const int nt_hi_c = 2 * tb + 1;
    int na = nt_hi_c - nt_lo + 1;
    if (na < 0) na = 0; if (na > 8) na = 8;
    const int r1 = tb * 16 + (lane >> 2);
    const int r2 = r1 + 8;

    float sacc[8][4];
#pragma unroll
    for (int j = 0; j < 8; ++j)
#pragma unroll
        for (int q = 0; q < 4; ++q) sacc[j][q] = 0.f;
    {
        const unsigned aqb = smb + Q_HI_B + (unsigned)((tb * 16 + (lane & 15)) * QK_PITCH_B)
                           + (lane >> 4) * 16;
        const unsigned akb = smb + K_HI_B + (unsigned)(((lane & 7)) * QK_PITCH_B)
                           + ((lane >> 3) & 1) * 16;
#pragma unroll
        for (int kg = 0; kg < 4; ++kg) {
            unsigned qh[4], ql[4];
            LDMX4(qh, aqb + kg * 32);
            LDMX4(ql, aqb + kg * 32 + (Q_LO_B - Q_HI_B));
#pragma unroll
            for (int j = 0; j < 8; ++j) {
                if (j < na) {
                    int nt = nt_lo + j;
                    unsigned kh[2], kl[2];
                    unsigned ka = akb + (unsigned)(nt * 8 * QK_PITCH_B) + kg * 32;
                    LDMX2(kh, ka);
                    LDMX2(kl, ka + (K_LO_B - K_HI_B));
                    mma_bf16(sacc[j], qh, kh[0], kh[1]);
                    mma_bf16(sacc[j], ql, kh[0], kh[1]);
                    mma_bf16(sacc[j], qh, kl[0], kl[1]);
                }
            }
        }
    }

    float* smax = (float*)((char*)data + STATS_B);
    float* ssum = (float*)((char*)data + STATS_B + 1024);
    float m1l = -INFINITY, m2l = -INFINITY;
#pragma unroll
    for (int j = 0; j < 8; ++j) {
        if (j < na) {
            int c = (nt_lo + j) * 8 + 2 * (lane & 3);
            if (c > r1)     sacc[j][0] = -INFINITY;
            if (c + 1 > r1) sacc[j][1] = -INFINITY;
            if (c > r2)     sacc[j][2] = -INFINITY;
            if (c + 1 > r2) sacc[j][3] = -INFINITY;
            m1l = fmaxf(m1l, fmaxf(sacc[j][0], sacc[j][1]));
            m2l = fmaxf(m2l, fmaxf(sacc[j][2], sacc[j][3]));
        }
    }
    m1l = fmaxf(m1l, __shfl_xor_sync(0xffffffffu, m1l, 1));
    m1l = fmaxf(m1l, __shfl_xor_sync(0xffffffffu, m1l, 2));
    m2l = fmaxf(m2l, __shfl_xor_sync(0xffffffffu, m2l, 1));
    m2l = fmaxf(m2l, __shfl_xor_sync(0xffffffffu, m2l, 2));
    if ((lane & 3) == 0) { smax[r1 * 2 + nh] = m1l; smax[r2 * 2 + nh] = m2l; }
    __syncthreads();
    float m1 = fmaxf(smax[r1 * 2], smax[r1 * 2 + 1]);
    float m2 = fmaxf(smax[r2 * 2], smax[r2 * 2 + 1]);
    float s1 = 0.f, s2 = 0.f;
#pragma unroll
    for (int j = 0; j < 8; ++j) {
        if (j < na) {
            sacc[j][0] = __expf(sacc[j][0] - m1);
            sacc[j][1] = __expf(sacc[j][1] - m1);
            sacc[j][2] = __expf(sacc[j][2] - m2);
            sacc[j][3] = __expf(sacc[j][3] - m2);
            s1 += sacc[j][0] + sacc[j][1];
            s2 += sacc[j][2] + sacc[j][3];
        }
    }
    s1 += __shfl_xor_sync(0xffffffffu, s1, 1);
    s1 += __shfl_xor_sync(0xffffffffu, s1, 2);
    s2 += __shfl_xor_sync(0xffffffffu, s2, 1);
    s2 += __shfl_xor_sync(0xffffffffu, s2, 2);
    if ((lane & 3) == 0) { ssum[r1 * 2 + nh] = s1; ssum[r2 * 2 + nh] = s2; }
    __syncthreads();
    float inv1 = 1.f / (ssum[r1 * 2] + ssum[r1 * 2 + 1]);
    float inv2 = 1.f / (ssum[r2 * 2] + ssum[r2 * 2 + 1]);

    unsigned phi[16], plo[16];
#pragma unroll
    for (int j = 0; j < 8; ++j) {
        if (j < na) {
            split2(sacc[j][0] * inv1, sacc[j][1] * inv1, phi[2 * j],     plo[2 * j]);
            split2(sacc[j][2] * inv2, sacc[j][3] * inv2, phi[2 * j + 1], plo[2 * j + 1]);
        } else {
            phi[2 * j] = 0; plo[2 * j] = 0; phi[2 * j + 1] = 0; plo[2 * j + 1] = 0;
        }
    }

    float oacc[8][4];
#pragma unroll
    for (int t = 0; t < 8; ++t)
#pragma unroll
        for (int q = 0; q < 4; ++q) oacc[t][q] = 0.f;
    {
        const unsigned avb = smb + VT_HI_B + (unsigned)((lane & 7) * VT_PITCH_B)
                           + ((lane >> 3) & 1) * 16;
#pragma unroll
        for (int j = 0; j < 8; j += 2) {
            if (j < na) {
                int kg = nt_lo + j;
#pragma unroll
                for (int th = 0; th < 8; ++th) {
                    unsigned vh[2], vl[2];
                    unsigned va = avb + (unsigned)(th * 8 * VT_PITCH_B) + kg * 16;
                    LDMX2(vh, va);
                    LDMX2(vl, va + (VT_LO_B - VT_HI_B));
                    mma_bf16_k8(oacc[th], phi[2 * j],     phi[2 * j + 1],     vh[0]);
                    mma_bf16_k8(oacc[th], plo[2 * j],     plo[2 * j + 1],     vh[0]);
                    mma_bf16_k8(oacc[th], phi[2 * j],     phi[2 * j + 1],     vl[0]);
                    mma_bf16_k8(oacc[th], phi[2 * j + 2], phi[2 * j + 3],     vh[1]);
                    mma_bf16_k8(oacc[th], plo[2 * j + 2], plo[2 * j + 3],     vh[1]);
                    mma_bf16_k8(oacc[th], phi[2 * j + 2], phi[2 * j + 3],     vl[1]);
                }
            }
        }
    }

    {
        float* obuf = (float*)((char*)data + OBUF_B) + tb * 16 * OB_PITCH;
        int rl = lane >> 2;
        int hc = 2 * (lane & 3);
        if (nh == 0) {
#pragma unroll
            for (int th = 0; th < 8; ++th) {
                int h = th * 8 + hc;
                *(float2*)&obuf[rl * OB_PITCH + h]       = make_float2(oacc[th][0], oacc[th][1]);
                *(float2*)&obuf[(rl + 8) * OB_PITCH + h] = make_float2(oacc[th][2], oacc[th][3]);
            }
        }
        __syncthreads();
        if (nh == 1) {
            float* ob = out + (size_t)b * TT * HH;
#pragma unroll
            for (int th = 0; th < 8; ++th) {
                int h = th * 8 + hc;
                float2 p1 = *(float2*)&obuf[rl * OB_PITCH + h];
                float2 p2 = *(float2*)&obuf[(rl + 8) * OB_PITCH + h];
                *(float2*)&ob[r1 * HH + h] = make_float2(p1.x + oacc[th][0], p1.y + oacc[th][1]);
                *(float2*)&ob[r2 * HH + h] = make_float2(p2.x + oacc[th][2], p2.y + oacc[th][3]);
            }
        }
    }
}

extern "C" void kernel_launch(void* const* d_in, const int* in_sizes, int n_in,
                              void* d_out, int out_size)
{
    const float* x  = (const float*)d_in[0];
    const float* Wk = (const float*)d_in[1];
    const float* Wq = (const float*)d_in[2];
    const float* Wv = (const float*)d_in[3];
    float* out = (float*)d_out;

    static int smem_set = 0;
    if (!smem_set) {
        cudaFuncSetAttribute(head_attn_mma,
                             cudaFuncAttributeMaxDynamicSharedMemorySize,
                             SMEM_BYTES);
        smem_set = 1;
    }
    prep_w<<<(NK16 * NTILES * 32 + 255) / 256, 256>>>(Wk, Wq, Wv);
    head_attn_mma<<<BB, 512, SMEM_BYTES>>>(x, out);
}

// round 17
// speedup vs baseline: 1.0186x; 1.0013x over previous
#include <cuda_runtime.h>
#include <cuda_bf16.h>
#include <math.h>
#include <stdint.h>

// ---------------- problem constants ----------------
#define BB   1024
#define TT   128
#define CC   1024
#define HH   64
#define N3   192
#define KCH  64
#define NCHUNKS (CC/KCH)    // 16
#define NK16 (CC/16)        // 64
#define NTILES (N3/8)       // 24

// ---------------- smem layout (byte offsets) ----------------
#define XS_PITCH   36
#define XS_HALF_B  18432
#define XS_BUF_B   36864
#define BST_B      73728
#define BCHUNK_B   49152
#define Q_HI_B   0
#define Q_LO_B   18432
#define K_HI_B   36864
#define K_LO_B   55296
#define VT_HI_B  73728
#define VT_LO_B  91136
#define STATS_B  108544
#define OBUF_B   0
#define OB_PITCH 66
#define SMEM_BYTES 172032
#define QK_PITCH_B 144
#define VT_PITCH_B 272

__device__ __align__(16) uint4 Bfrag_g[NK16 * NTILES * 32];

// ---------------- helpers ----------------
__device__ __forceinline__ uint32_t smem_u32(const void* p) {
    uint32_t a;
    asm("{ .reg .u64 t; cvta.to.shared.u64 t, %1; cvt.u32.u64 %0, t; }" : "=r"(a) : "l"(p));
    return a;
}
__device__ __forceinline__ void split2(float a, float b, unsigned& hi, unsigned& lo) {
    __nv_bfloat16 ha = __float2bfloat16_rn(a);
    __nv_bfloat16 hb = __float2bfloat16_rn(b);
    float ra = a - __bfloat162float(ha);
    float rb = b - __bfloat162float(hb);
    __nv_bfloat16 la = __float2bfloat16_rn(ra);
    __nv_bfloat16 lb = __float2bfloat16_rn(rb);
    hi = ((unsigned)__bfloat16_as_ushort(hb) << 16) | __bfloat16_as_ushort(ha);
    lo = ((unsigned)__bfloat16_as_ushort(lb) << 16) | __bfloat16_as_ushort(la);
}
__device__ __forceinline__ void mma_bf16(float* d, const unsigned* a,
                                         unsigned b0, unsigned b1) {
    asm volatile(
        "mma.sync.aligned.m16n8k16.row.col.f32.bf16.bf16.f32 "
        "{%0,%1,%2,%3}, {%4,%5,%6,%7}, {%8,%9}, {%0,%1,%2,%3};"
        : "+f"(d[0]), "+f"(d[1]), "+f"(d[2]), "+f"(d[3])
        : "r"(a[0]), "r"(a[1]), "r"(a[2]), "r"(a[3]), "r"(b0), "r"(b1));
}
__device__ __forceinline__ void mma_bf16_k8(float* d, unsigned a0, unsigned a1,
                                            unsigned b0) {
    asm volatile(
        "mma.sync.aligned.m16n8k8.row.col.f32.bf16.bf16.f32 "
        "{%0,%1,%2,%3}, {%4,%5}, {%6}, {%0,%1,%2,%3};"
        : "+f"(d[0]), "+f"(d[1]), "+f"(d[2]), "+f"(d[3])
        : "r"(a0), "r"(a1), "r"(b0));
}
#define LDMX4(r, addr) asm volatile( \
    "ldmatrix.sync.aligned.m8n8.x4.shared.b16 {%0,%1,%2,%3}, [%4];" \
    : "=r"((r)[0]), "=r"((r)[1]), "=r"((r)[2]), "=r"((r)[3]) : "r"(addr))
#define LDMX2(r, addr) asm volatile( \
    "ldmatrix.sync.aligned.m8n8.x2.shared.b16 {%0,%1}, [%2];" \
    : "=r"((r)[0]), "=r"((r)[1]) : "r"(addr))
#define CP_ASYNC16(smem_addr, gptr) asm volatile( \
    "cp.async.cg.shared.global [%0], [%1], 16;" :: "r"(smem_addr), "l"(gptr))
#define CP_COMMIT() asm volatile("cp.async.commit_group;" ::: "memory")
#define CP_WAIT0()  asm volatile("cp.async.wait_group 0;" ::: "memory")

// ---------------- prep kernel ----------------
__global__ void prep_w(const float* __restrict__ Wk,
                       const float* __restrict__ Wq,
                       const float* __restrict__ Wv)
{
    int i = blockIdx.x * blockDim.x + threadIdx.x;
    if (i >= NK16 * NTILES * 32) return;
    int lane = i & 31;
    int rest = i >> 5;
    int nt   = rest % NTILES;
    int k16  = rest / NTILES;
    int n    = nt * 8 + (lane >> 2);
    int mat  = n >> 6;
    int h    = n & 63;
    const float* W = (mat == 0) ? Wq : (mat == 1) ? Wk : Wv;
    int kb = k16 * 16 + 2 * (lane & 3);
    float w00 = W[kb * HH + h];
    float w01 = W[(kb + 1) * HH + h];
    float w10 = W[(kb + 8) * HH + h];
    float w11 = W[(kb + 9) * HH + h];
    uint4 v;
    split2(w00, w01, v.x, v.z);
    split2(w10, w11, v.y, v.w);
    Bfrag_g[i] = v;
}

// ---------------- main fused kernel ----------------
__global__ __launch_bounds__(512, 1)
void head_attn_mma(const float* __restrict__ x, float* __restrict__ out)
{
    extern __shared__ float data[];
    const uint32_t smb = smem_u32(data);

    const int b     = blockIdx.x;
    const int tid   = threadIdx.x;
    const int warp  = tid >> 5;
    const int lane  = tid & 31;
    const int warpM = warp >> 2;
    const int warpN = warp & 3;
    const float* xb = x + (size_t)b * TT * CC;

    // ---- Phase 1: QKV projection (bf16 m16n8k16, 3-term split) ----
    float acc[2][6][4];
#pragma unroll
    for (int bk = 0; bk < 2; ++bk)
#pragma unroll
        for (int nt = 0; nt < 6; ++nt)
#pragma unroll
            for (int j = 0; j < 4; ++j) acc[bk][nt][j] = 0.f;

    const int prow = tid >> 2;
    const int q0   = tid & 3;
    float4 pf[4];
#pragma unroll
    for (int e = 0; e < 4; ++e)
        pf[e] = ((const float4*)(xb + (size_t)prow * CC))[q0 + 4 * e];

    {
        const uint4* g0 = Bfrag_g;
        unsigned s0 = smb + BST_B;
#pragma unroll
        for (int t = 0; t < 6; ++t) {
            int i = tid + t * 512;
            CP_ASYNC16(s0 + i * 16, g0 + i);
        }
        CP_COMMIT();
    }
    {
        unsigned* hi0 = (unsigned*)data;
        unsigned* lo0 = (unsigned*)((char*)data + XS_HALF_B);
#pragma unroll
        for (int e = 0; e < 4; ++e) {
            int j4 = q0 + 4 * e;
            unsigned h, l;
            split2(pf[e].x, pf[e].y, h, l);
            hi0[prow * XS_PITCH + j4 * 2]     = h; lo0[prow * XS_PITCH + j4 * 2]     = l;
            split2(pf[e].z, pf[e].w, h, l);
            hi0[prow * XS_PITCH + j4 * 2 + 1] = h; lo0[prow * XS_PITCH + j4 * 2 + 1] = l;
        }
    }
#pragma unroll
    for (int e = 0; e < 4; ++e)
        pf[e] = ((const float4*)(xb + (size_t)prow * CC + KCH))[q0 + 4 * e];
    CP_WAIT0();
    __syncthreads();

    const unsigned a_off = (unsigned)((warpM * 32 + (lane & 15)) * (XS_PITCH * 4)
                                      + (lane >> 4) * 16);

    for (int ch = 0; ch < NCHUNKS; ++ch) {
        if (ch + 1 < NCHUNKS) {
            const uint4* gsrc = Bfrag_g + (size_t)(ch + 1) * 4 * NTILES * 32;
            unsigned sdst = smb + BST_B + (unsigned)(((ch + 1) & 1) * BCHUNK_B);
#pragma unroll
            for (int t = 0; t < 6; ++t) {
                int i = tid + t * 512;
                CP_ASYNC16(sdst + i * 16, gsrc + i);
            }
        }
        CP_COMMIT();

        if (ch + 1 < NCHUNKS) {
            unsigned* hin = (unsigned*)((char*)data + ((ch + 1) & 1) * XS_BUF_B);
            unsigned* lon = (unsigned*)((char*)hin + XS_HALF_B);
#pragma unroll
            for (int e = 0; e < 4; ++e) {
                int j4 = q0 + 4 * e;
                unsigned h, l;
                split2(pf[e].x, pf[e].y, h, l);
                hin[prow * XS_PITCH + j4 * 2]     = h; lon[prow * XS_PITCH + j4 * 2]     = l;
                split2(pf[e].z, pf[e].w, h, l);
                hin[prow * XS_PITCH + j4 * 2 + 1] = h; lon[prow * XS_PITCH + j4 * 2 + 1] = l;
            }
        }
        if (ch + 2 < NCHUNKS) {
            int c0n = (ch + 2) * KCH;
#pragma unroll
            for (int e = 0; e < 4; ++e)
                pf[e] = ((const float4*)(xb + (size_t)prow * CC + c0n))[q0 + 4 * e];
        }

        // compute chunk ch: term-major over 3-nt groups -> RAW distance 6 MMAs
        const unsigned hib = smb + (unsigned)((ch & 1) * XS_BUF_B);
        const unsigned lob = hib + XS_HALF_B;
        const uint4* bbase = (const uint4*)((char*)data + BST_B + (ch & 1) * BCHUNK_B);
#pragma unroll
        for (int g = 0; g < 4; ++g) {
            unsigned ah0[4], al0[4], ah1[4], al1[4];
            unsigned ad  = hib + a_off + g * 32;
            unsigned al_ = lob + a_off + g * 32;
            LDMX4(ah0, ad);
            LDMX4(al0, al_);
            LDMX4(ah1, ad + 16 * (XS_PITCH * 4));
            LDMX4(al1, al_ + 16 * (XS_PITCH * 4));

            const uint4* bp = bbase + (g * NTILES + warpN * 6) * 32 + lane;
#pragma unroll
            for (int half = 0; half < 2; ++half) {
                const int n0 = half * 3;
                uint4 b0 = bp[(n0 + 0) * 32];
                uint4 b1 = bp[(n0 + 1) * 32];
                uint4 b2 = bp[(n0 + 2) * 32];
                // hi*hi (6 distinct accumulators)
                mma_bf16(acc[0][n0 + 0], ah0, b0.x, b0.y);
                mma_bf16(acc[0][n0 + 1], ah0, b1.x, b1.y);
                mma_bf16(acc[0][n0 + 2], ah0, b2.x, b2.y);
                mma_bf16(acc[1][n0 + 0], ah1, b0.x, b0.y);
                mma_bf16(acc[1][n0 + 1], ah1, b1.x, b1.y);
                mma_bf16(acc[1][n0 + 2], ah1, b2.x, b2.y);
                // lo*hi
                mma_bf16(acc[0][n0 + 0], al0, b0.x, b0.y);
                mma_bf16(acc[0][n0 + 1], al0, b1.x, b1.y);
                mma_bf16(acc[0][n0 + 2], al0, b2.x, b2.y);
                mma_bf16(acc[1][n0 + 0], al1, b0.x, b0.y);
                mma_bf16(acc[1][n0 + 1], al1, b1.x, b1.y);
                mma_bf16(acc[1][n0 + 2], al1, b2.x, b2.y);
                // hi*lo
                mma_bf16(acc[0][n0 + 0], ah0, b0.z, b0.w);
                mma_bf16(acc[0][n0 + 1], ah0, b1.z, b1.w);
                mma_bf16(acc[0][n0 + 2], ah0, b2.z, b2.w);
                mma_bf16(acc[1][n0 + 0], ah1, b0.z, b0.w);
                mma_bf16(acc[1][n0 + 1], ah1, b1.z, b1.w);
                mma_bf16(acc[1][n0 + 2], ah1, b2.z, b2.w);
            }
        }

        CP_WAIT0();
        __syncthreads();
    }

    // ---- scatter: Q/K -> bf16 hi/lo rows; V -> vt[h][s] bf16 hi/lo ----
    {
        char* base = (char*)data;
#pragma unroll
        for (int bk = 0; bk < 2; ++bk) {
#pragma unroll
            for (int nt = 0; nt < 6; ++nt) {
                int r   = warpM * 32 + bk * 16 + (lane >> 2);
                int n   = warpN * 48 + nt * 8 + (lane & 3) * 2;
                int mat = n >> 6;
                int h   = n & 63;
                unsigned hiA, loA, hiB, loB;
                split2(acc[bk][nt][0], acc[bk][nt][1], hiA, loA);
                split2(acc[bk][nt][2], acc[bk][nt][3], hiB, loB);
                if (mat == 0) {
                    *(unsigned*)(base + Q_HI_B + r * QK_PITCH_B + h * 2)       = hiA;
                    *(unsigned*)(base + Q_LO_B + r * QK_PITCH_B + h * 2)       = loA;
                    *(unsigned*)(base + Q_HI_B + (r + 8) * QK_PITCH_B + h * 2) = hiB;
                    *(unsigned*)(base + Q_LO_B + (r + 8) * QK_PITCH_B + h * 2) = loB;
                } else if (mat == 1) {
                    *(unsigned*)(base + K_HI_B + r * QK_PITCH_B + h * 2)       = hiA;
                    *(unsigned*)(base + K_LO_B + r * QK_PITCH_B + h * 2)       = loA;
                    *(unsigned*)(base + K_HI_B + (r + 8) * QK_PITCH_B + h * 2) = hiB;
                    *(unsigned*)(base + K_LO_B + (r + 8) * QK_PITCH_B + h * 2) = loB;
                } else {
                    *(unsigned short*)(base + VT_HI_B + h * VT_PITCH_B + r * 2)             = (unsigned short)(hiA & 0xFFFF);
                    *(unsigned short*)(base + VT_HI_B + (h + 1) * VT_PITCH_B + r * 2)       = (unsigned short)(hiA >> 16);
                    *(unsigned short*)(base + VT_LO_B + h * VT_PITCH_B + r * 2)             = (unsigned short)(loA & 0xFFFF);
                    *(unsigned short*)(base + VT_LO_B + (h + 1) * VT_PITCH_B + r * 2)       = (unsigned short)(loA >> 16);
                    *(unsigned short*)(base + VT_HI_B + h * VT_PITCH_B + (r + 8) * 2)       = (unsigned short)(hiB & 0xFFFF);
                    *(unsigned short*)(base + VT_HI_B + (h + 1) * VT_PITCH_B + (r + 8) * 2) = (unsigned short)(hiB >> 16);
                    *(unsigned short*)(base + VT_LO_B + h * VT_PITCH_B + (r + 8) * 2)       = (unsigned short)(loB & 0xFFFF);
                    *(unsigned short*)(base + VT_LO_B + (h + 1) * VT_PITCH_B + (r + 8) * 2) = (unsigned short)(loB >> 16);
                }
            }
        }
    }
    __syncthreads();

    // ================= FA2-style tail (interleaved MMA chains) =================
    const int tb = warp >> 1;
    const int nh = warp & 1;
    const int nt_lo = nh * 8;
    const int nt_hi_c = 2 * tb + 1;
    int na = nt_hi_c - nt_lo + 1;
    if (na < 0) na = 0; if (na > 8) na = 8;
    const int r1 = tb * 16 + (lane >> 2);
    const int r2 = r1 + 8;

    // ---- Phase 2: S = Q @ K^T into registers (j-pair interleaved) ----
    float sacc[8][4];
#pragma unroll
    for (int j = 0; j < 8; ++j)
#pragma unroll
        for (int q = 0; q < 4; ++q) sacc[j][q] = 0.f;
    {
        const unsigned aqb = smb + Q_HI_B + (unsigned)((tb * 16 + (lane & 15)) * QK_PITCH_B)
                           + (lane >> 4) * 16;
        const unsigned akb = smb + K_HI_B + (unsigned)(((lane & 7)) * QK_PITCH_B)
                           + ((lane >> 3) & 1) * 16;
#pragma unroll
        for (int kg = 0; kg < 4; ++kg) {
            unsigned qh[4], ql[4];
            LDMX4(qh, aqb + kg * 32);
            LDMX4(ql, aqb + kg * 32 + (Q_LO_B - Q_HI_B));
#pragma unroll
            for (int j = 0; j < 8; j += 2) {
                if (j < na) {    // na is even -> j and j+1 both valid
                    unsigned ka = akb + (unsigned)((nt_lo + j) * 8 * QK_PITCH_B) + kg * 32;
                    unsigned kb_ = ka + (unsigned)(8 * QK_PITCH_B);
                    unsigned kha[2], kla[2], khb[2], klb[2];
                    LDMX2(kha, ka);
                    LDMX2(kla, ka + (K_LO_B - K_HI_B));
                    LDMX2(khb, kb_);
                    LDMX2(klb, kb_ + (K_LO_B - K_HI_B));
                    mma_bf16(sacc[j],     qh, kha[0], kha[1]);
                    mma_bf16(sacc[j + 1], qh, khb[0], khb[1]);
                    mma_bf16(sacc[j],     ql, kha[0], kha[1]);
                    mma_bf16(sacc[j + 1], ql, khb[0], khb[1]);
                    mma_bf16(sacc[j],     qh, kla[0], kla[1]);
                    mma_bf16(sacc[j + 1], qh, klb[0], klb[1]);
                }
            }
        }
    }

    // ---- Phase 3: causal mask + softmax ----
    float* smax = (float*)((char*)data + STATS_B);
    float* ssum = (float*)((char*)data + STATS_B + 1024);
    float m1l = -INFINITY, m2l = -INFINITY;
#pragma unroll
    for (int j = 0; j < 8; ++j) {
        if (j < na) {
            int c = (nt_lo + j) * 8 + 2 * (lane & 3);
            if (c > r1)     sacc[j][0] = -INFINITY;
            if (c + 1 > r1) sacc[j][1] = -INFINITY;
            if (c > r2)     sacc[j][2] = -INFINITY;
            if (c + 1 > r2) sacc[j][3] = -INFINITY;
            m1l = fmaxf(m1l, fmaxf(sacc[j][0], sacc[j][1]));
            m2l = fmaxf(m2l, fmaxf(sacc[j][2], sacc[j][3]));
        }
    }
    m1l = fmaxf(m1l, __shfl_xor_sync(0xffffffffu, m1l, 1));
    m1l = fmaxf(m1l, __shfl_xor_sync(0xffffffffu, m1l, 2));
    m2l = fmaxf(m2l, __shfl_xor_sync(0xffffffffu, m2l, 1));
    m2l = fmaxf(m2l, __shfl_xor_sync(0xffffffffu, m2l, 2));
    if ((lane & 3) == 0) { smax[r1 * 2 + nh] = m1l; smax[r2 * 2 + nh] = m2l; }
    __syncthreads();
    float m1 = fmaxf(smax[r1 * 2], smax[r1 * 2 + 1]);
    float m2 = fmaxf(smax[r2 * 2], smax[r2 * 2 + 1]);
    float s1 = 0.f, s2 = 0.f;
#pragma unroll
    for (int j = 0; j < 8; ++j) {
        if (j < na) {
            sacc[j][0] = __expf(sacc[j][0] - m1);
            sacc[j][1] = __expf(sacc[j][1] - m1);
            sacc[j][2] = __expf(sacc[j][2] - m2);
            sacc[j][3] = __expf(sacc[j][3] - m2);
            s1 += sacc[j][0] + sacc[j][1];
            s2 += sacc[j][2] + sacc[j][3];
        }
    }
    s1 += __shfl_xor_sync(0xffffffffu, s1, 1);
    s1 += __shfl_xor_sync(0xffffffffu, s1, 2);
    s2 += __shfl_xor_sync(0xffffffffu, s2, 1);
    s2 += __shfl_xor_sync(0xffffffffu, s2, 2);
    if ((lane & 3) == 0) { ssum[r1 * 2 + nh] = s1; ssum[r2 * 2 + nh] = s2; }
    __syncthreads();
    float inv1 = 1.f / (ssum[r1 * 2] + ssum[r1 * 2 + 1]);
    float inv2 = 1.f / (ssum[r2 * 2] + ssum[r2 * 2 + 1]);

    unsigned phi[16], plo[16];
#pragma unroll
    for (int j = 0; j < 8; ++j) {
        if (j < na) {
            split2(sacc[j][0] * inv1, sacc[j][1] * inv1, phi[2 * j],     plo[2 * j]);
            split2(sacc[j][2] * inv2, sacc[j][3] * inv2, phi[2 * j + 1], plo[2 * j + 1]);
        } else {
            phi[2 * j] = 0; plo[2 * j] = 0; phi[2 * j + 1] = 0; plo[2 * j + 1] = 0;
        }
    }

    // ---- Phase 4: O = P @ V via m16n8k8 (th-pair interleaved) ----
    float oacc[8][4];
#pragma unroll
    for (int t = 0; t < 8; ++t)
#pragma unroll
        for (int q = 0; q < 4; ++q) oacc[t][q] = 0.f;
    {
        const unsigned avb = smb + VT_HI_B + (unsigned)((lane & 7) * VT_PITCH_B)
                           + ((lane >> 3) & 1) * 16;
#pragma unroll
        for (int j = 0; j < 8; j += 2) {
            if (j < na) {
#pragma unroll
                for (int th = 0; th < 8; th += 2) {
                    unsigned vha[2], vla[2], vhb[2], vlb[2];
                    unsigned va = avb + (unsigned)(th * 8 * VT_PITCH_B) + (nt_lo + j) * 16;
                    unsigned vb = va + (unsigned)(8 * VT_PITCH_B);
                    LDMX2(vha, va);
                    LDMX2(vla, va + (VT_LO_B - VT_HI_B));
                    LDMX2(vhb, vb);
                    LDMX2(vlb, vb + (VT_LO_B - VT_HI_B));
                    mma_bf16_k8(oacc[th],     phi[2 * j],     phi[2 * j + 1], vha[0]);
                    mma_bf16_k8(oacc[th + 1], phi[2 * j],     phi[2 * j + 1], vhb[0]);
                    mma_bf16_k8(oacc[th],     plo[2 * j],     plo[2 * j + 1], vha[0]);
                    mma_bf16_k8(oacc[th + 1], plo[2 * j],     plo[2 * j + 1], vhb[0]);
                    mma_bf16_k8(oacc[th],     phi[2 * j],     phi[2 * j + 1], vla[0]);
                    mma_bf16_k8(oacc[th + 1], phi[2 * j],     phi[2 * j + 1], vlb[0]);
                    mma_bf16_k8(oacc[th],     phi[2 * j + 2], phi[2 * j + 3], vha[1]);
                    mma_bf16_k8(oacc[th + 1], phi[2 * j + 2], phi[2 * j + 3], vhb[1]);
                    mma_bf16_k8(oacc[th],     plo[2 * j + 2], plo[2 * j + 3], vha[1]);
                    mma_bf16_k8(oacc[th + 1], plo[2 * j + 2], plo[2 * j + 3], vhb[1]);
                    mma_bf16_k8(oacc[th],     phi[2 * j + 2], phi[2 * j + 3], vla[1]);
                    mma_bf16_k8(oacc[th + 1], phi[2 * j + 2], phi[2 * j + 3], vlb[1]);
                }
            }
        }
    }

    // ---- combine n-half partials via obuf, then STG ----
    {
        float* obuf = (float*)((char*)data + OBUF_B) + tb * 16 * OB_PITCH;
        int rl = lane >> 2;
        int hc = 2 * (lane & 3);
        if (nh == 0) {
#pragma unroll
            for (int th = 0; th < 8; ++th) {
                int h = th * 8 + hc;
                *(float2*)&obuf[rl * OB_PITCH + h]       = make_float2(oacc[th][0], oacc[th][1]);
                *(float2*)&obuf[(rl + 8) * OB_PITCH + h] = make_float2(oacc[th][2], oacc[th][3]);
            }
        }
        __syncthreads();
        if (nh == 1) {
            float* ob = out + (size_t)b * TT * HH;
#pragma unroll
            for (int th = 0; th < 8; ++th) {
                int h = th * 8 + hc;
                float2 p1 = *(float2*)&obuf[rl * OB_PITCH + h];
                float2 p2 = *(float2*)&obuf[(rl + 8) * OB_PITCH + h];
                *(float2*)&ob[r1 * HH + h] = make_float2(p1.x + oacc[th][0], p1.y + oacc[th][1]);
                *(float2*)&ob[r2 * HH + h] = make_float2(p2.x + oacc[th][2], p2.y + oacc[th][3]);
            }
        }
    }
}

extern "C" void kernel_launch(void* const* d_in, const int* in_sizes, int n_in,
                              void* d_out, int out_size)
{
    const float* x  = (const float*)d_in[0];
    const float* Wk = (const float*)d_in[1];
    const float* Wq = (const float*)d_in[2];
    const float* Wv = (const float*)d_in[3];
    float* out = (float*)d_out;

    static int smem_set = 0;
    if (!smem_set) {
        cudaFuncSetAttribute(head_attn_mma,
                             cudaFuncAttributeMaxDynamicSharedMemorySize,
                             SMEM_BYTES);
        smem_set = 1;
    }
    prep_w<<<(NK16 * NTILES * 32 + 255) / 256, 256>>>(Wk, Wq, Wv);
    head_attn_mma<<<BB, 512, SMEM_BYTES>>>(x, out);
}